// round 1
// baseline (speedup 1.0000x reference)
#include <cuda_runtime.h>

#define N_NODES 50000
#define N_EDGES 800000
#define F_IN    128
#define HID     64
#define TOT_E   (N_EDGES + N_NODES)
#define NEG_SLOPE 0.2f
#define SCAN_T  512
#define SCAN_NB ((N_NODES + SCAN_T - 1) / SCAN_T)   // 98

// -------- scratch (static device globals; no runtime allocation) --------
__device__ float g_h[N_NODES * HID];        // 12.8 MB  post-GEMM features
__device__ float g_asrc[N_NODES];
__device__ float g_adst[N_NODES];
__device__ int   g_deg[N_NODES];
__device__ int   g_fill[N_NODES];
__device__ int   g_rowptr[N_NODES + 1];
__device__ int   g_csr[TOT_E];
__device__ float g_s1[N_NODES];
__device__ float g_s2[N_NODES];
__device__ int   g_bsum[SCAN_NB];
__device__ int   g_boff[SCAN_NB];
__device__ int   g_idx64;

// -------- edge index dtype detection (int64 vs silently-demoted int32) --------
__global__ void k_detect(const long long* e) {
    long long mx = 0;
    for (int i = 0; i < 16; i++) {
        long long v = e[i];
        if (v < 0) v = -v;
        if (v > mx) mx = v;
    }
    // true int64 node ids are < 2^31; int32 data read as int64 pairs is huge
    g_idx64 = (mx < (1LL << 31)) ? 1 : 0;
}

__device__ __forceinline__ int eidx(const void* ep, long long i) {
    if (g_idx64) return (int)((const long long*)ep)[i];
    return ((const int*)ep)[i];
}

// -------- 1) GEMM h = x @ W  +  per-node attention dots --------
__global__ void __launch_bounds__(256) k_gemm(const float* __restrict__ x,
                                              const float* __restrict__ W,
                                              const float* __restrict__ attS,
                                              const float* __restrict__ attD) {
    __shared__ __align__(16) float sW[F_IN * HID];   // 32 KB
    __shared__ __align__(16) float sx[16 * F_IN];    // 8 KB
    int tx = threadIdx.x, ty = threadIdx.y;
    int tid = ty * 16 + tx;
    for (int i = tid; i < F_IN * HID; i += 256) sW[i] = W[i];
    int row0 = blockIdx.x * 16;
    for (int i = tid; i < 16 * F_IN; i += 256) sx[i] = x[row0 * F_IN + i];
    __syncthreads();

    float a0 = 0.f, a1 = 0.f, a2 = 0.f, a3 = 0.f;
#pragma unroll 16
    for (int k = 0; k < F_IN; k++) {
        float xv = sx[ty * F_IN + k];
        float4 wv = *(const float4*)&sW[k * HID + tx * 4];
        a0 += xv * wv.x; a1 += xv * wv.y; a2 += xv * wv.z; a3 += xv * wv.w;
    }
    int row = row0 + ty;
    *(float4*)&g_h[row * HID + tx * 4] = make_float4(a0, a1, a2, a3);

    int c = tx * 4;
    float pa = a0 * attS[c] + a1 * attS[c + 1] + a2 * attS[c + 2] + a3 * attS[c + 3];
    float pb = a0 * attD[c] + a1 * attD[c + 1] + a2 * attD[c + 2] + a3 * attD[c + 3];
#pragma unroll
    for (int off = 8; off >= 1; off >>= 1) {
        pa += __shfl_down_sync(0xffffffffu, pa, off, 16);
        pb += __shfl_down_sync(0xffffffffu, pb, off, 16);
    }
    if (tx == 0) { g_asrc[row] = pa; g_adst[row] = pb; }
}

// -------- 2) CSR build --------
__global__ void k_init() {
    int i = blockIdx.x * blockDim.x + threadIdx.x;
    if (i < N_NODES) { g_deg[i] = 1; g_fill[i] = 1; }  // slot 0 reserved for self loop
}

__global__ void k_hist(const void* e) {
    int i = blockIdx.x * blockDim.x + threadIdx.x;
    if (i < N_EDGES) atomicAdd(&g_deg[eidx(e, (long long)N_EDGES + i)], 1);
}

__global__ void k_scan1() {
    __shared__ int s[SCAN_T];
    int i = blockIdx.x * SCAN_T + threadIdx.x;
    s[threadIdx.x] = (i < N_NODES) ? g_deg[i] : 0;
    __syncthreads();
    for (int off = SCAN_T / 2; off > 0; off >>= 1) {
        if (threadIdx.x < off) s[threadIdx.x] += s[threadIdx.x + off];
        __syncthreads();
    }
    if (threadIdx.x == 0) g_bsum[blockIdx.x] = s[0];
}

__global__ void k_scan2() {
    __shared__ int s[SCAN_NB];
    if (threadIdx.x < SCAN_NB) s[threadIdx.x] = g_bsum[threadIdx.x];
    __syncthreads();
    if (threadIdx.x == 0) {
        int run = 0;
        for (int i = 0; i < SCAN_NB; i++) { int v = s[i]; s[i] = run; run += v; }
    }
    __syncthreads();
    if (threadIdx.x < SCAN_NB) g_boff[threadIdx.x] = s[threadIdx.x];
}

__global__ void k_scan3() {
    __shared__ int s[SCAN_T];
    int t = threadIdx.x;
    int i = blockIdx.x * SCAN_T + t;
    int v = (i < N_NODES) ? g_deg[i] : 0;
    s[t] = v;
    __syncthreads();
    for (int off = 1; off < SCAN_T; off <<= 1) {   // Hillis-Steele inclusive
        int add = (t >= off) ? s[t - off] : 0;
        __syncthreads();
        s[t] += add;
        __syncthreads();
    }
    if (i < N_NODES) {
        int incl = s[t] + g_boff[blockIdx.x];
        int excl = incl - v;
        g_rowptr[i] = excl;
        g_csr[excl] = i;                        // self loop in slot 0
        if (i == N_NODES - 1) g_rowptr[N_NODES] = incl;
    }
}

__global__ void k_scatter(const void* e) {
    int i = blockIdx.x * blockDim.x + threadIdx.x;
    if (i < N_EDGES) {
        int s = eidx(e, i);
        int d = eidx(e, (long long)N_EDGES + i);
        int pos = g_rowptr[d] + atomicAdd(&g_fill[d], 1);
        g_csr[pos] = s;
    }
}

// -------- 3) per-dst-node softmax + aggregation + ELU + fc projection --------
__global__ void __launch_bounds__(256) k_agg(const float* __restrict__ bias,
                                             const float* __restrict__ fcw) {
    int node = blockIdx.x * 8 + (threadIdx.x >> 5);
    if (node >= N_NODES) return;
    int lane = threadIdx.x & 31;
    int beg = g_rowptr[node], end = g_rowptr[node + 1];
    float ad = g_adst[node];

    float m = -1e30f;
    for (int i = beg + lane; i < end; i += 32) {
        float e = g_asrc[g_csr[i]] + ad;
        e = (e > 0.f) ? e : NEG_SLOPE * e;
        m = fmaxf(m, e);
    }
#pragma unroll
    for (int off = 16; off; off >>= 1) m = fmaxf(m, __shfl_xor_sync(0xffffffffu, m, off));

    float ss = 0.f;
    for (int i = beg + lane; i < end; i += 32) {
        float e = g_asrc[g_csr[i]] + ad;
        e = (e > 0.f) ? e : NEG_SLOPE * e;
        ss += __expf(e - m);
    }
#pragma unroll
    for (int off = 16; off; off >>= 1) ss += __shfl_xor_sync(0xffffffffu, ss, off);
    float inv = 1.0f / ss;

    float ax = 0.f, ay = 0.f;
    const float2* h2 = (const float2*)g_h;
    for (int i = beg; i < end; i++) {
        int s = g_csr[i];
        float e = g_asrc[s] + ad;
        e = (e > 0.f) ? e : NEG_SLOPE * e;
        float al = __expf(e - m) * inv;
        float2 hv = h2[s * 32 + lane];     // coalesced 256B per edge
        ax += al * hv.x; ay += al * hv.y;
    }
    int c = lane * 2;
    ax += bias[c]; ay += bias[c + 1];
    ax = (ax > 0.f) ? ax : expm1f(ax);     // ELU
    ay = (ay > 0.f) ? ay : expm1f(ay);

    float p1 = ax * fcw[c] + ay * fcw[c + 1];
    float p2 = ax * fcw[HID + c] + ay * fcw[HID + c + 1];
#pragma unroll
    for (int off = 16; off; off >>= 1) {
        p1 += __shfl_xor_sync(0xffffffffu, p1, off);
        p2 += __shfl_xor_sync(0xffffffffu, p2, off);
    }
    if (lane == 0) { g_s1[node] = p1; g_s2[node] = p2; }
}

// -------- 4) edge scores = s1[src] + s2[dst] + b --------
__global__ void k_scores(const void* e, const float* __restrict__ fcb,
                         float* __restrict__ out) {
    int i = blockIdx.x * blockDim.x + threadIdx.x;
    if (i < N_EDGES)
        out[i] = g_s1[eidx(e, i)] + g_s2[eidx(e, (long long)N_EDGES + i)] + fcb[0];
}

extern "C" void kernel_launch(void* const* d_in, const int* in_sizes, int n_in,
                              void* d_out, int out_size) {
    const float* x    = (const float*)d_in[0];
    const void*  ei   = d_in[1];
    const float* W    = (const float*)d_in[2];
    const float* attS = (const float*)d_in[3];
    const float* attD = (const float*)d_in[4];
    const float* bias = (const float*)d_in[5];
    const float* fcw  = (const float*)d_in[6];
    const float* fcb  = (const float*)d_in[7];
    float* out = (float*)d_out;

    k_detect<<<1, 1>>>((const long long*)ei);
    k_gemm<<<N_NODES / 16, dim3(16, 16)>>>(x, W, attS, attD);
    k_init<<<(N_NODES + 255) / 256, 256>>>();
    k_hist<<<(N_EDGES + 255) / 256, 256>>>(ei);
    k_scan1<<<SCAN_NB, SCAN_T>>>();
    k_scan2<<<1, 128>>>();
    k_scan3<<<SCAN_NB, SCAN_T>>>();
    k_scatter<<<(N_EDGES + 255) / 256, 256>>>(ei);
    k_agg<<<(N_NODES + 7) / 8, 256>>>(bias, fcw);
    k_scores<<<(N_EDGES + 255) / 256, 256>>>(ei, fcb, out);
}

// round 2
// speedup vs baseline: 1.3750x; 1.3750x over previous
#include <cuda_runtime.h>

#define N_NODES 50000
#define N_EDGES 800000
#define F_IN    128
#define HID     64
#define TOT_E   (N_EDGES + N_NODES)
#define NEG_SLOPE 0.2f
#define SCAN_T  512
#define SCAN_NB ((N_NODES + SCAN_T - 1) / SCAN_T)   // 98
#define GR      64     // gemm rows per block
#define KC      32     // gemm k-chunk

// -------- scratch (static device globals; no runtime allocation) --------
__device__ float g_h[N_NODES * HID];        // 12.8 MB  post-GEMM features
__device__ float g_asrc[N_NODES];
__device__ float g_adst[N_NODES];
__device__ int   g_deg[N_NODES];
__device__ int   g_fill[N_NODES];
__device__ int   g_rowptr[N_NODES + 1];
__device__ int   g_csr[TOT_E];
__device__ float g_wt[TOT_E];               // exp(leakyrelu(e)) per CSR slot
__device__ int   g_src[N_EDGES];            // int32 copies of edge index
__device__ int   g_dst[N_EDGES];
__device__ float g_s1[N_NODES];
__device__ float g_s2[N_NODES];
__device__ int   g_bsum[SCAN_NB];
__device__ int   g_boff[SCAN_NB];
__device__ int   g_idx64;

// -------- 0) dtype detect + deg/fill init --------
__global__ void k_pre(const long long* e) {
    int i = blockIdx.x * blockDim.x + threadIdx.x;
    if (i == 0) {
        long long mx = 0;
        for (int j = 0; j < 16; j++) {
            long long v = e[j];
            if (v < 0) v = -v;
            if (v > mx) mx = v;
        }
        g_idx64 = (mx < (1LL << 31)) ? 1 : 0;   // int32 read as int64 -> huge values
    }
    if (i < N_NODES) { g_deg[i] = 1; g_fill[i] = 1; }  // slot 0 = self loop
}

// -------- 1) GEMM h = x @ W  (8 rows x 4 cols per thread)  + attention dots --------
__global__ void __launch_bounds__(128) k_gemm(const float* __restrict__ x,
                                              const float* __restrict__ W,
                                              const float* __restrict__ attS,
                                              const float* __restrict__ attD) {
    __shared__ __align__(16) float sW[F_IN * HID];   // 32 KB
    __shared__ __align__(16) float sxT[KC * GR];     // 8 KB, k-major
    int tx = threadIdx.x;            // 0..15 -> 4 cols each
    int ty = threadIdx.y;            // 0..7  -> 8 rows each
    int tid = ty * 16 + tx;
    int row0 = blockIdx.x * GR;

    for (int i = tid; i < F_IN * HID / 4; i += 128)
        ((float4*)sW)[i] = ((const float4*)W)[i];

    float acc[8][4];
#pragma unroll
    for (int r = 0; r < 8; r++)
#pragma unroll
        for (int c = 0; c < 4; c++) acc[r][c] = 0.f;

    int lr = tid & 63;       // row this thread stages
    int lg = tid >> 6;       // 0/1 -> which k-quads

    for (int kc = 0; kc < F_IN; kc += KC) {
        __syncthreads();
#pragma unroll
        for (int j = 0; j < 4; j++) {
            int ko = lg * 4 + j * 8;
            float4 v = make_float4(0.f, 0.f, 0.f, 0.f);
            int row = row0 + lr;
            if (row < N_NODES) v = *(const float4*)&x[row * F_IN + kc + ko];
            sxT[(ko + 0) * GR + lr] = v.x;
            sxT[(ko + 1) * GR + lr] = v.y;
            sxT[(ko + 2) * GR + lr] = v.z;
            sxT[(ko + 3) * GR + lr] = v.w;
        }
        __syncthreads();
#pragma unroll
        for (int kk = 0; kk < KC; kk++) {
            float4 wv = *(const float4*)&sW[(kc + kk) * HID + tx * 4];
            float4 xa = *(const float4*)&sxT[kk * GR + ty * 8];
            float4 xb = *(const float4*)&sxT[kk * GR + ty * 8 + 4];
            float xs[8] = {xa.x, xa.y, xa.z, xa.w, xb.x, xb.y, xb.z, xb.w};
#pragma unroll
            for (int r = 0; r < 8; r++) {
                acc[r][0] += xs[r] * wv.x;
                acc[r][1] += xs[r] * wv.y;
                acc[r][2] += xs[r] * wv.z;
                acc[r][3] += xs[r] * wv.w;
            }
        }
    }

    int c0 = tx * 4;
    float aS0 = attS[c0], aS1 = attS[c0 + 1], aS2 = attS[c0 + 2], aS3 = attS[c0 + 3];
    float aD0 = attD[c0], aD1 = attD[c0 + 1], aD2 = attD[c0 + 2], aD3 = attD[c0 + 3];
#pragma unroll
    for (int r = 0; r < 8; r++) {
        int row = row0 + ty * 8 + r;
        bool ok = (row < N_NODES);
        if (ok)
            *(float4*)&g_h[row * HID + c0] =
                make_float4(acc[r][0], acc[r][1], acc[r][2], acc[r][3]);
        float pa = acc[r][0] * aS0 + acc[r][1] * aS1 + acc[r][2] * aS2 + acc[r][3] * aS3;
        float pb = acc[r][0] * aD0 + acc[r][1] * aD1 + acc[r][2] * aD2 + acc[r][3] * aD3;
#pragma unroll
        for (int off = 8; off >= 1; off >>= 1) {
            pa += __shfl_down_sync(0xffffffffu, pa, off, 16);
            pb += __shfl_down_sync(0xffffffffu, pb, off, 16);
        }
        if (tx == 0 && ok) { g_asrc[row] = pa; g_adst[row] = pb; }
    }
}

// -------- 2) int64->int32 convert + dst histogram (4 edges/thread ILP) --------
__global__ void k_convhist(const void* e) {
    int t = blockIdx.x * blockDim.x + threadIdx.x;
    int base = t * 4;
    if (base >= N_EDGES) return;
    int i64 = g_idx64;
#pragma unroll
    for (int j = 0; j < 4; j++) {
        long long i = base + j;
        int s, d;
        if (i64) {
            s = (int)((const long long*)e)[i];
            d = (int)((const long long*)e)[N_EDGES + i];
        } else {
            s = ((const int*)e)[i];
            d = ((const int*)e)[N_EDGES + i];
        }
        g_src[i] = s;
        g_dst[i] = d;
        atomicAdd(&g_deg[d], 1);
    }
}

// -------- 3) scan of degrees -> rowptr, seed self loops --------
__global__ void k_scan1() {
    __shared__ int s[SCAN_T];
    int i = blockIdx.x * SCAN_T + threadIdx.x;
    s[threadIdx.x] = (i < N_NODES) ? g_deg[i] : 0;
    __syncthreads();
    for (int off = SCAN_T / 2; off > 0; off >>= 1) {
        if (threadIdx.x < off) s[threadIdx.x] += s[threadIdx.x + off];
        __syncthreads();
    }
    if (threadIdx.x == 0) g_bsum[blockIdx.x] = s[0];
}

__global__ void k_scan2() {
    __shared__ int s[SCAN_NB];
    if (threadIdx.x < SCAN_NB) s[threadIdx.x] = g_bsum[threadIdx.x];
    __syncthreads();
    if (threadIdx.x == 0) {
        int run = 0;
        for (int i = 0; i < SCAN_NB; i++) { int v = s[i]; s[i] = run; run += v; }
    }
    __syncthreads();
    if (threadIdx.x < SCAN_NB) g_boff[threadIdx.x] = s[threadIdx.x];
}

__global__ void k_scan3() {
    __shared__ int s[SCAN_T];
    int t = threadIdx.x;
    int i = blockIdx.x * SCAN_T + t;
    int v = (i < N_NODES) ? g_deg[i] : 0;
    s[t] = v;
    __syncthreads();
    for (int off = 1; off < SCAN_T; off <<= 1) {   // Hillis-Steele inclusive
        int add = (t >= off) ? s[t - off] : 0;
        __syncthreads();
        s[t] += add;
        __syncthreads();
    }
    if (i < N_NODES) {
        int incl = s[t] + g_boff[blockIdx.x];
        int excl = incl - v;
        g_rowptr[i] = excl;
        g_csr[excl] = i;                        // self loop in slot 0
        float e = g_asrc[i] + g_adst[i];
        e = (e > 0.f) ? e : NEG_SLOPE * e;
        g_wt[excl] = __expf(e);
        if (i == N_NODES - 1) g_rowptr[N_NODES] = incl;
    }
}

// -------- 4) scatter edges into CSR + precompute softmax weights --------
__global__ void k_scatter() {
    int i = blockIdx.x * blockDim.x + threadIdx.x;
    if (i < N_EDGES) {
        int s = g_src[i];
        int d = g_dst[i];
        float e = g_asrc[s] + g_adst[d];
        e = (e > 0.f) ? e : NEG_SLOPE * e;
        int pos = g_rowptr[d] + atomicAdd(&g_fill[d], 1);
        g_csr[pos] = s;
        g_wt[pos] = __expf(e);
    }
}

// -------- 5) single-pass softmax aggregation + ELU + fc projection --------
__global__ void __launch_bounds__(256) k_agg(const float* __restrict__ bias,
                                             const float* __restrict__ fcw) {
    int node = blockIdx.x * 8 + (threadIdx.x >> 5);
    if (node >= N_NODES) return;
    int lane = threadIdx.x & 31;
    int beg = g_rowptr[node], end = g_rowptr[node + 1];

    float ws = 0.f, ax = 0.f, ay = 0.f;
    const float2* h2 = (const float2*)g_h;
    for (int i = beg; i < end; i++) {
        int s = g_csr[i];
        float w = g_wt[i];
        ws += w;
        float2 hv = h2[s * 32 + lane];     // coalesced 256B per edge
        ax += w * hv.x;
        ay += w * hv.y;
    }
    float inv = 1.0f / ws;                 // ws identical across lanes
    ax *= inv; ay *= inv;

    int c = lane * 2;
    ax += bias[c]; ay += bias[c + 1];
    ax = (ax > 0.f) ? ax : expm1f(ax);     // ELU
    ay = (ay > 0.f) ? ay : expm1f(ay);

    float p1 = ax * fcw[c] + ay * fcw[c + 1];
    float p2 = ax * fcw[HID + c] + ay * fcw[HID + c + 1];
#pragma unroll
    for (int off = 16; off; off >>= 1) {
        p1 += __shfl_xor_sync(0xffffffffu, p1, off);
        p2 += __shfl_xor_sync(0xffffffffu, p2, off);
    }
    if (lane == 0) { g_s1[node] = p1; g_s2[node] = p2; }
}

// -------- 6) edge scores = s1[src] + s2[dst] + b  (4 edges/thread) --------
__global__ void k_scores(const float* __restrict__ fcb, float* __restrict__ out) {
    int t = blockIdx.x * blockDim.x + threadIdx.x;
    int base = t * 4;
    if (base >= N_EDGES) return;
    float b = fcb[0];
    int4 s4 = *(const int4*)&g_src[base];
    int4 d4 = *(const int4*)&g_dst[base];
    float4 o;
    o.x = g_s1[s4.x] + g_s2[d4.x] + b;
    o.y = g_s1[s4.y] + g_s2[d4.y] + b;
    o.z = g_s1[s4.z] + g_s2[d4.z] + b;
    o.w = g_s1[s4.w] + g_s2[d4.w] + b;
    *(float4*)&out[base] = o;
}

extern "C" void kernel_launch(void* const* d_in, const int* in_sizes, int n_in,
                              void* d_out, int out_size) {
    const float* x    = (const float*)d_in[0];
    const void*  ei   = d_in[1];
    const float* W    = (const float*)d_in[2];
    const float* attS = (const float*)d_in[3];
    const float* attD = (const float*)d_in[4];
    const float* bias = (const float*)d_in[5];
    const float* fcw  = (const float*)d_in[6];
    const float* fcb  = (const float*)d_in[7];
    float* out = (float*)d_out;

    k_pre<<<(N_NODES + 255) / 256, 256>>>((const long long*)ei);
    k_gemm<<<(N_NODES + GR - 1) / GR, dim3(16, 8)>>>(x, W, attS, attD);
    k_convhist<<<(N_EDGES / 4 + 255) / 256, 256>>>(ei);
    k_scan1<<<SCAN_NB, SCAN_T>>>();
    k_scan2<<<1, 128>>>();
    k_scan3<<<SCAN_NB, SCAN_T>>>();
    k_scatter<<<(N_EDGES + 255) / 256, 256>>>();
    k_agg<<<(N_NODES + 7) / 8, 256>>>(bias, fcw);
    k_scores<<<(N_EDGES / 4 + 255) / 256, 256>>>(fcb, out);
}

// round 3
// speedup vs baseline: 1.3820x; 1.0051x over previous
#include <cuda_runtime.h>

#define N_NODES 50000
#define N_EDGES 800000
#define F_IN    128
#define HID     64
#define TOT_E   (N_EDGES + N_NODES)
#define NEG_SLOPE 0.2f
#define SCAN_T  512
#define SCAN_NB ((N_NODES + SCAN_T - 1) / SCAN_T)   // 98
#define GR      64     // gemm rows per block
#define KC      32     // gemm k-chunk

// -------- scratch (static device globals; no runtime allocation) --------
__device__ float g_h[N_NODES * HID];        // 12.8 MB  post-GEMM features
__device__ float g_asrc[N_NODES];
__device__ float g_adst[N_NODES];
__device__ int   g_deg[N_NODES];
__device__ int   g_fill[N_NODES];
__device__ int   g_rowptr[N_NODES + 1];
__device__ int   g_csr[TOT_E];
__device__ float g_wt[TOT_E];               // exp(leakyrelu(e)) per CSR slot
__device__ int   g_src[N_EDGES];            // int32 copies of edge index
__device__ int   g_dst[N_EDGES];
__device__ float g_s1[N_NODES];
__device__ float g_s2[N_NODES];
__device__ int   g_bsum[SCAN_NB];
__device__ int   g_boff[SCAN_NB];
__device__ int   g_idx64;

// -------- 0) dtype detect + deg/fill init --------
__global__ void k_pre(const long long* e) {
    int i = blockIdx.x * blockDim.x + threadIdx.x;
    if (i == 0) {
        long long mx = 0;
        for (int j = 0; j < 16; j++) {
            long long v = e[j];
            if (v < 0) v = -v;
            if (v > mx) mx = v;
        }
        g_idx64 = (mx < (1LL << 31)) ? 1 : 0;   // int32 read as int64 -> huge values
    }
    if (i < N_NODES) { g_deg[i] = 1; g_fill[i] = 1; }  // slot 0 = self loop
}

// -------- 1) GEMM h = x @ W  (8 rows x 4 cols per thread)  + attention dots --------
__global__ void __launch_bounds__(128) k_gemm(const float* __restrict__ x,
                                              const float* __restrict__ W,
                                              const float* __restrict__ attS,
                                              const float* __restrict__ attD) {
    __shared__ __align__(16) float sW[F_IN * HID];   // 32 KB
    __shared__ __align__(16) float sxT[KC * GR];     // 8 KB, k-major
    int tx = threadIdx.x;            // 0..15 -> 4 cols each
    int ty = threadIdx.y;            // 0..7  -> 8 rows each
    int tid = ty * 16 + tx;
    int row0 = blockIdx.x * GR;

    for (int i = tid; i < F_IN * HID / 4; i += 128)
        ((float4*)sW)[i] = ((const float4*)W)[i];

    float acc[8][4];
#pragma unroll
    for (int r = 0; r < 8; r++)
#pragma unroll
        for (int c = 0; c < 4; c++) acc[r][c] = 0.f;

    int lr = tid & 63;       // row this thread stages
    int lg = tid >> 6;       // 0/1 -> which k-quads

    for (int kc = 0; kc < F_IN; kc += KC) {
        __syncthreads();
#pragma unroll
        for (int j = 0; j < 4; j++) {
            int ko = lg * 4 + j * 8;
            float4 v = make_float4(0.f, 0.f, 0.f, 0.f);
            int row = row0 + lr;
            if (row < N_NODES) v = *(const float4*)&x[row * F_IN + kc + ko];
            sxT[(ko + 0) * GR + lr] = v.x;
            sxT[(ko + 1) * GR + lr] = v.y;
            sxT[(ko + 2) * GR + lr] = v.z;
            sxT[(ko + 3) * GR + lr] = v.w;
        }
        __syncthreads();
#pragma unroll
        for (int kk = 0; kk < KC; kk++) {
            float4 wv = *(const float4*)&sW[(kc + kk) * HID + tx * 4];
            float4 xa = *(const float4*)&sxT[kk * GR + ty * 8];
            float4 xb = *(const float4*)&sxT[kk * GR + ty * 8 + 4];
            float xs[8] = {xa.x, xa.y, xa.z, xa.w, xb.x, xb.y, xb.z, xb.w};
#pragma unroll
            for (int r = 0; r < 8; r++) {
                acc[r][0] += xs[r] * wv.x;
                acc[r][1] += xs[r] * wv.y;
                acc[r][2] += xs[r] * wv.z;
                acc[r][3] += xs[r] * wv.w;
            }
        }
    }

    int c0 = tx * 4;
    float aS0 = attS[c0], aS1 = attS[c0 + 1], aS2 = attS[c0 + 2], aS3 = attS[c0 + 3];
    float aD0 = attD[c0], aD1 = attD[c0 + 1], aD2 = attD[c0 + 2], aD3 = attD[c0 + 3];
#pragma unroll
    for (int r = 0; r < 8; r++) {
        int row = row0 + ty * 8 + r;
        bool ok = (row < N_NODES);
        if (ok)
            *(float4*)&g_h[row * HID + c0] =
                make_float4(acc[r][0], acc[r][1], acc[r][2], acc[r][3]);
        float pa = acc[r][0] * aS0 + acc[r][1] * aS1 + acc[r][2] * aS2 + acc[r][3] * aS3;
        float pb = acc[r][0] * aD0 + acc[r][1] * aD1 + acc[r][2] * aD2 + acc[r][3] * aD3;
#pragma unroll
        for (int off = 8; off >= 1; off >>= 1) {
            pa += __shfl_down_sync(0xffffffffu, pa, off, 16);
            pb += __shfl_down_sync(0xffffffffu, pb, off, 16);
        }
        if (tx == 0 && ok) { g_asrc[row] = pa; g_adst[row] = pb; }
    }
}

// -------- 2) int64->int32 convert + dst histogram (4 edges/thread ILP) --------
__global__ void k_convhist(const void* e) {
    int t = blockIdx.x * blockDim.x + threadIdx.x;
    int base = t * 4;
    if (base >= N_EDGES) return;
    int i64 = g_idx64;
#pragma unroll
    for (int j = 0; j < 4; j++) {
        long long i = base + j;
        int s, d;
        if (i64) {
            s = (int)((const long long*)e)[i];
            d = (int)((const long long*)e)[N_EDGES + i];
        } else {
            s = ((const int*)e)[i];
            d = ((const int*)e)[N_EDGES + i];
        }
        g_src[i] = s;
        g_dst[i] = d;
        atomicAdd(&g_deg[d], 1);
    }
}

// -------- 3) scan of degrees -> rowptr, seed self loops --------
__global__ void k_scan1() {
    __shared__ int s[SCAN_T];
    int i = blockIdx.x * SCAN_T + threadIdx.x;
    s[threadIdx.x] = (i < N_NODES) ? g_deg[i] : 0;
    __syncthreads();
    for (int off = SCAN_T / 2; off > 0; off >>= 1) {
        if (threadIdx.x < off) s[threadIdx.x] += s[threadIdx.x + off];
        __syncthreads();
    }
    if (threadIdx.x == 0) g_bsum[blockIdx.x] = s[0];
}

__global__ void k_scan2() {
    __shared__ int s[SCAN_NB];
    if (threadIdx.x < SCAN_NB) s[threadIdx.x] = g_bsum[threadIdx.x];
    __syncthreads();
    if (threadIdx.x == 0) {
        int run = 0;
        for (int i = 0; i < SCAN_NB; i++) { int v = s[i]; s[i] = run; run += v; }
    }
    __syncthreads();
    if (threadIdx.x < SCAN_NB) g_boff[threadIdx.x] = s[threadIdx.x];
}

__global__ void k_scan3() {
    __shared__ int s[SCAN_T];
    int t = threadIdx.x;
    int i = blockIdx.x * SCAN_T + t;
    int v = (i < N_NODES) ? g_deg[i] : 0;
    s[t] = v;
    __syncthreads();
    for (int off = 1; off < SCAN_T; off <<= 1) {   // Hillis-Steele inclusive
        int add = (t >= off) ? s[t - off] : 0;
        __syncthreads();
        s[t] += add;
        __syncthreads();
    }
    if (i < N_NODES) {
        int incl = s[t] + g_boff[blockIdx.x];
        int excl = incl - v;
        g_rowptr[i] = excl;
        g_csr[excl] = i;                        // self loop in slot 0
        float e = g_asrc[i] + g_adst[i];
        e = (e > 0.f) ? e : NEG_SLOPE * e;
        g_wt[excl] = __expf(e);
        if (i == N_NODES - 1) g_rowptr[N_NODES] = incl;
    }
}

// -------- 4) scatter edges into CSR + precompute softmax weights --------
__global__ void k_scatter() {
    int i = blockIdx.x * blockDim.x + threadIdx.x;
    if (i < N_EDGES) {
        int s = g_src[i];
        int d = g_dst[i];
        float e = g_asrc[s] + g_adst[d];
        e = (e > 0.f) ? e : NEG_SLOPE * e;
        int pos = g_rowptr[d] + atomicAdd(&g_fill[d], 1);
        g_csr[pos] = s;
        g_wt[pos] = __expf(e);
    }
}

// -------- 5) single-pass softmax aggregation + ELU + fc projection --------
__global__ void __launch_bounds__(256) k_agg(const float* __restrict__ bias,
                                             const float* __restrict__ fcw) {
    int node = blockIdx.x * 8 + (threadIdx.x >> 5);
    if (node >= N_NODES) return;
    int lane = threadIdx.x & 31;
    int beg = g_rowptr[node], end = g_rowptr[node + 1];

    float ws = 0.f, ax = 0.f, ay = 0.f;
    const float2* h2 = (const float2*)g_h;
    for (int i = beg; i < end; i++) {
        int s = g_csr[i];
        float w = g_wt[i];
        ws += w;
        float2 hv = h2[s * 32 + lane];     // coalesced 256B per edge
        ax += w * hv.x;
        ay += w * hv.y;
    }
    float inv = 1.0f / ws;                 // ws identical across lanes
    ax *= inv; ay *= inv;

    int c = lane * 2;
    ax += bias[c]; ay += bias[c + 1];
    ax = (ax > 0.f) ? ax : expm1f(ax);     // ELU
    ay = (ay > 0.f) ? ay : expm1f(ay);

    float p1 = ax * fcw[c] + ay * fcw[c + 1];
    float p2 = ax * fcw[HID + c] + ay * fcw[HID + c + 1];
#pragma unroll
    for (int off = 16; off; off >>= 1) {
        p1 += __shfl_xor_sync(0xffffffffu, p1, off);
        p2 += __shfl_xor_sync(0xffffffffu, p2, off);
    }
    if (lane == 0) { g_s1[node] = p1; g_s2[node] = p2; }
}

// -------- 6) edge scores = s1[src] + s2[dst] + b  (4 edges/thread) --------
__global__ void k_scores(const float* __restrict__ fcb, float* __restrict__ out) {
    int t = blockIdx.x * blockDim.x + threadIdx.x;
    int base = t * 4;
    if (base >= N_EDGES) return;
    float b = fcb[0];
    int4 s4 = *(const int4*)&g_src[base];
    int4 d4 = *(const int4*)&g_dst[base];
    float4 o;
    o.x = g_s1[s4.x] + g_s2[d4.x] + b;
    o.y = g_s1[s4.y] + g_s2[d4.y] + b;
    o.z = g_s1[s4.z] + g_s2[d4.z] + b;
    o.w = g_s1[s4.w] + g_s2[d4.w] + b;
    *(float4*)&out[base] = o;
}

extern "C" void kernel_launch(void* const* d_in, const int* in_sizes, int n_in,
                              void* d_out, int out_size) {
    const float* x    = (const float*)d_in[0];
    const void*  ei   = d_in[1];
    const float* W    = (const float*)d_in[2];
    const float* attS = (const float*)d_in[3];
    const float* attD = (const float*)d_in[4];
    const float* bias = (const float*)d_in[5];
    const float* fcw  = (const float*)d_in[6];
    const float* fcb  = (const float*)d_in[7];
    float* out = (float*)d_out;

    k_pre<<<(N_NODES + 255) / 256, 256>>>((const long long*)ei);
    k_gemm<<<(N_NODES + GR - 1) / GR, dim3(16, 8)>>>(x, W, attS, attD);
    k_convhist<<<(N_EDGES / 4 + 255) / 256, 256>>>(ei);
    k_scan1<<<SCAN_NB, SCAN_T>>>();
    k_scan2<<<1, 128>>>();
    k_scan3<<<SCAN_NB, SCAN_T>>>();
    k_scatter<<<(N_EDGES + 255) / 256, 256>>>();
    k_agg<<<(N_NODES + 7) / 8, 256>>>(bias, fcw);
    k_scores<<<(N_EDGES / 4 + 255) / 256, 256>>>(fcb, out);
}